// round 2
// baseline (speedup 1.0000x reference)
#include <cuda_runtime.h>
#include <math.h>

// ---------------------------------------------------------------------------
// Problem constants (from reference)
// ---------------------------------------------------------------------------
#define BB   8
#define NQL  1024
#define DD   2048
#define HH   16
#define DHH  128
#define FFD  8192
#define RR   16
#define MQ   (BB*NQL)          // 8192 rows of x_q
#define LORA_SCALE 1.0f

// ---------------------------------------------------------------------------
// Scratch (device globals; allocation-free rule)
// ---------------------------------------------------------------------------
__device__ float g_rrms[MQ];                 // per-row 1/rms of x_q
__device__ float g_xbar[BB*DD];              // mean of rmsnorm(x_q) over seq
__device__ float g_logits[BB*4];
__device__ float g_gate[BB*4];
__device__ float g_Q[(long long)MQ*DD];
__device__ float g_K[(long long)MQ*DD];
__device__ float g_V[(long long)MQ*DD];
__device__ float g_S[(long long)BB*HH*NQL*1024];   // scores, max NK=1024 (512MB)
__device__ float g_O[(long long)MQ*DD];
__device__ float g_T[(long long)MQ*DD];      // generic [8192,2048] temp
__device__ float g_delta[(long long)MQ*DD];
__device__ float g_x1[(long long)MQ*DD];
__device__ float g_h[(long long)MQ*DD];
__device__ float g_G[(long long)MQ*FFD];     // gate path (256MB)
__device__ float g_U[(long long)MQ*FFD];     // up path   (256MB)
__device__ float g_lt[(long long)MQ*RR];     // lora intermediate

// ---------------------------------------------------------------------------
// Generic strided-batched SGEMM: C = alpha * A*op(B) (+ bias) (+ beta*C)
// A: [M,K] row-major (lda). op(B): TB=0 -> B[K,N] row-major (ldb);
//                            TB=1 -> B stored [N,K] row-major (ldb), used as B^T.
// Batch z: offset = (z/zdiv)*s1 + (z%zdiv)*s2 for each of A,B,C.
// 128x128 block tile, 8x8 per thread, BK=8, 256 threads.
// ---------------------------------------------------------------------------
template <int TB>
__global__ __launch_bounds__(256)
void sgemm_k(int M, int N, int K,
             const float* __restrict__ A, int lda, long long sA1, long long sA2,
             const float* __restrict__ B, int ldb, long long sB1, long long sB2,
             float* __restrict__ C, int ldc, long long sC1, long long sC2,
             int zdiv, float alpha, float beta, const float* __restrict__ bias)
{
    const int BM = 128, BN = 128, BK = 8;
    __shared__ float As[BK][BM];
    __shared__ float Bs[BK][BN];

    int z = blockIdx.z;
    A += (long long)(z / zdiv) * sA1 + (long long)(z % zdiv) * sA2;
    B += (long long)(z / zdiv) * sB1 + (long long)(z % zdiv) * sB2;
    C += (long long)(z / zdiv) * sC1 + (long long)(z % zdiv) * sC2;

    int bm = blockIdx.y * BM;
    int bn = blockIdx.x * BN;
    int tid = threadIdx.x;
    int tx = tid & 15;          // n-dim
    int ty = tid >> 4;          // m-dim

    float acc[8][8];
#pragma unroll
    for (int i = 0; i < 8; i++)
#pragma unroll
        for (int j = 0; j < 8; j++) acc[i][j] = 0.f;

    int ktiles = (K + BK - 1) / BK;
    for (int kt = 0; kt < ktiles; kt++) {
        int k0 = kt * BK;
        // load A tile (128x8) -> As[k][m]
#pragma unroll
        for (int i = 0; i < 4; i++) {
            int idx = tid + i * 256;
            int m = idx >> 3, k = idx & 7;
            int gm = bm + m, gk = k0 + k;
            As[k][m] = (gm < M && gk < K) ? A[(long long)gm * lda + gk] : 0.f;
        }
        // load B tile -> Bs[k][n]
#pragma unroll
        for (int i = 0; i < 4; i++) {
            int idx = tid + i * 256;
            if (TB) {
                int n = idx >> 3, k = idx & 7;
                int gn = bn + n, gk = k0 + k;
                Bs[k][n] = (gn < N && gk < K) ? B[(long long)gn * ldb + gk] : 0.f;
            } else {
                int k = idx >> 7, n = idx & 127;
                int gk = k0 + k, gn = bn + n;
                Bs[k][n] = (gk < K && gn < N) ? B[(long long)gk * ldb + gn] : 0.f;
            }
        }
        __syncthreads();

#pragma unroll
        for (int k = 0; k < BK; k++) {
            float4 a0 = *reinterpret_cast<const float4*>(&As[k][ty * 8]);
            float4 a1 = *reinterpret_cast<const float4*>(&As[k][ty * 8 + 4]);
            float4 b0 = *reinterpret_cast<const float4*>(&Bs[k][tx * 8]);
            float4 b1 = *reinterpret_cast<const float4*>(&Bs[k][tx * 8 + 4]);
            float ra[8] = {a0.x, a0.y, a0.z, a0.w, a1.x, a1.y, a1.z, a1.w};
            float rb[8] = {b0.x, b0.y, b0.z, b0.w, b1.x, b1.y, b1.z, b1.w};
#pragma unroll
            for (int i = 0; i < 8; i++)
#pragma unroll
                for (int j = 0; j < 8; j++)
                    acc[i][j] = fmaf(ra[i], rb[j], acc[i][j]);
        }
        __syncthreads();
    }

#pragma unroll
    for (int i = 0; i < 8; i++) {
        int gm = bm + ty * 8 + i;
        if (gm >= M) continue;
#pragma unroll
        for (int j = 0; j < 8; j++) {
            int gn = bn + tx * 8 + j;
            if (gn >= N) continue;
            float v = alpha * acc[i][j];
            if (bias) v += bias[gn];
            long long off = (long long)gm * ldc + gn;
            if (beta != 0.f) v += beta * C[off];
            C[off] = v;
        }
    }
}

// ---------------------------------------------------------------------------
// Row helpers
// ---------------------------------------------------------------------------
__global__ void rowrms_k(const float* __restrict__ X, float* __restrict__ rrms, int ncols)
{
    int row = blockIdx.x;
    const float* p = X + (long long)row * ncols;
    __shared__ float red[256];
    float s = 0.f;
    for (int c = threadIdx.x; c < ncols; c += 256) { float v = p[c]; s += v * v; }
    red[threadIdx.x] = s; __syncthreads();
    for (int st = 128; st > 0; st >>= 1) {
        if (threadIdx.x < st) red[threadIdx.x] += red[threadIdx.x + st];
        __syncthreads();
    }
    if (threadIdx.x == 0) rrms[row] = rsqrtf(red[0] / ncols + 1e-6f);
}

// xbar[b,d] = (1/NQ) * sum_n w[d] * x[b,n,d] * rrms[b,n]
__global__ void xbar_k(const float* __restrict__ X, const float* __restrict__ rrms,
                       const float* __restrict__ w, float* __restrict__ xbar)
{
    int idx = blockIdx.x * blockDim.x + threadIdx.x;
    if (idx >= BB * DD) return;
    int b = idx / DD, d = idx % DD;
    const float* xp = X + (long long)b * NQL * DD + d;
    const float* rp = rrms + b * NQL;
    float s = 0.f;
    for (int n = 0; n < NQL; n++) s += xp[(long long)n * DD] * rp[n];
    xbar[idx] = w[d] * s * (1.f / NQL);
}

__global__ void router_logits_k(const float* __restrict__ xbar, const float* __restrict__ W,
                                const float* __restrict__ bias, float* __restrict__ logits)
{
    int b = blockIdx.x >> 2, e = blockIdx.x & 3;
    __shared__ float red[256];
    float s = 0.f;
    for (int k = threadIdx.x; k < DD; k += 256) s += xbar[b * DD + k] * W[k * 4 + e];
    red[threadIdx.x] = s; __syncthreads();
    for (int st = 128; st > 0; st >>= 1) {
        if (threadIdx.x < st) red[threadIdx.x] += red[threadIdx.x + st];
        __syncthreads();
    }
    if (threadIdx.x == 0) logits[b * 4 + e] = red[0] + bias[e];
}

__global__ void gate_k(const float* __restrict__ logits, float* __restrict__ gate)
{
    int b = threadIdx.x;
    if (b >= BB) return;
    float l[4]; float mx = -1e30f;
    for (int e = 0; e < 4; e++) { l[e] = logits[b * 4 + e]; mx = fmaxf(mx, l[e]); }
    float s = 0.f;
    for (int e = 0; e < 4; e++) { l[e] = expf(l[e] - mx); s += l[e]; }
    for (int e = 0; e < 4; e++) l[e] /= s;
    int i1 = 0;
    for (int e = 1; e < 4; e++) if (l[e] > l[i1]) i1 = e;
    int i2 = -1;
    for (int e = 0; e < 4; e++) if (e != i1 && (i2 < 0 || l[e] > l[i2])) i2 = e;
    float denom = l[i1] + l[i2] + 1e-10f;
    float g[4] = {0.f, 0.f, 0.f, 0.f};
    g[i1] = l[i1] / denom;
    g[i2] = l[i2] / denom;
    for (int e = 0; e < 4; e++) gate[b * 4 + e] = g[e];
}

__global__ void softmax_rows_k(float* __restrict__ S, int ncols)
{
    int row = blockIdx.x;
    float* p = S + (long long)row * ncols;
    __shared__ float sm[1024];
    __shared__ float red[256];
    int tid = threadIdx.x;
    float mx = -1e30f;
    for (int c = tid; c < ncols; c += 256) { float v = p[c]; sm[c] = v; mx = fmaxf(mx, v); }
    red[tid] = mx; __syncthreads();
    for (int st = 128; st > 0; st >>= 1) {
        if (tid < st) red[tid] = fmaxf(red[tid], red[tid + st]);
        __syncthreads();
    }
    mx = red[0]; __syncthreads();
    float sum = 0.f;
    for (int c = tid; c < ncols; c += 256) { float e = __expf(sm[c] - mx); sm[c] = e; sum += e; }
    red[tid] = sum; __syncthreads();
    for (int st = 128; st > 0; st >>= 1) {
        if (tid < st) red[tid] += red[tid + st];
        __syncthreads();
    }
    float inv = 1.f / red[0];
    __syncthreads();
    for (int c = tid; c < ncols; c += 256) p[c] = sm[c] * inv;
}

__global__ void rmsnorm_k(const float* __restrict__ X, const float* __restrict__ w,
                          float* __restrict__ Y, int ncols)
{
    int row = blockIdx.x;
    const float* p = X + (long long)row * ncols;
    float* q = Y + (long long)row * ncols;
    __shared__ float red[256];
    float s = 0.f;
    for (int c = threadIdx.x; c < ncols; c += 256) { float v = p[c]; s += v * v; }
    red[threadIdx.x] = s; __syncthreads();
    for (int st = 128; st > 0; st >>= 1) {
        if (threadIdx.x < st) red[threadIdx.x] += red[threadIdx.x + st];
        __syncthreads();
    }
    float scale = rsqrtf(red[0] / ncols + 1e-6f);
    __syncthreads();
    for (int c = threadIdx.x; c < ncols; c += 256) q[c] = w[c] * p[c] * scale;
}

// ---------------------------------------------------------------------------
// Elementwise fusions
// ---------------------------------------------------------------------------
__global__ void adddelta_k(const float* __restrict__ T, const float* __restrict__ gate,
                           int e, int first, float* __restrict__ delta)
{
    int idx = blockIdx.x * blockDim.x + threadIdx.x;
    if (idx >= MQ * DD) return;
    int b = idx >> 21;   // / (NQ*D) = 2^21
    float g = gate[b * 4 + e];
    float v = g * T[idx];
    delta[idx] = first ? v : (delta[idx] + v);
}

__global__ void x1_k(const float* __restrict__ xq, const float* __restrict__ delta,
                     const float* __restrict__ alpha1, float* __restrict__ x1)
{
    int idx = blockIdx.x * blockDim.x + threadIdx.x;
    if (idx >= MQ * DD) return;
    float s = 1.f / (1.f + expf(-alpha1[0]));
    x1[idx] = xq[idx] + s * delta[idx];
}

__global__ void silu_add_k(float* __restrict__ G, const float* __restrict__ U, long long n)
{
    long long idx = (long long)blockIdx.x * blockDim.x + threadIdx.x;
    if (idx >= n) return;
    float g = G[idx];
    G[idx] = g / (1.f + expf(-g)) + U[idx];
}

__global__ void out_k(const float* __restrict__ x1, const float* __restrict__ T,
                      const float* __restrict__ alpha2, float* __restrict__ out)
{
    int idx = blockIdx.x * blockDim.x + threadIdx.x;
    if (idx >= MQ * DD) return;
    float s = 1.f / (1.f + expf(-alpha2[0]));
    out[idx] = x1[idx] + s * T[idx];
}

// ---------------------------------------------------------------------------
// Host-side GEMM launcher
// ---------------------------------------------------------------------------
static void gemm(bool transB, int M, int N, int K,
                 const float* A, int lda, long long sA1, long long sA2,
                 const float* B, int ldb, long long sB1, long long sB2,
                 float* C, int ldc, long long sC1, long long sC2,
                 int Z, int zdiv, float alpha, float beta, const float* bias)
{
    dim3 grid((N + 127) / 128, (M + 127) / 128, Z);
    if (transB)
        sgemm_k<1><<<grid, 256>>>(M, N, K, A, lda, sA1, sA2, B, ldb, sB1, sB2,
                                  C, ldc, sC1, sC2, zdiv, alpha, beta, bias);
    else
        sgemm_k<0><<<grid, 256>>>(M, N, K, A, lda, sA1, sA2, B, ldb, sB1, sB2,
                                  C, ldc, sC1, sC2, zdiv, alpha, beta, bias);
}

template <typename T>
static T* sym(const void* s)
{
    void* p = nullptr;
    cudaGetSymbolAddress(&p, (const void*)s);
    return (T*)p;
}

// ---------------------------------------------------------------------------
// kernel_launch
// ---------------------------------------------------------------------------
extern "C" void kernel_launch(void* const* d_in, const int* in_sizes, int n_in,
                              void* d_out, int out_size)
{
    const float* x_q      = (const float*)d_in[0];
    const float* z_a      = (const float*)d_in[1];
    const float* z_v      = (const float*)d_in[2];
    const float* z_av     = (const float*)d_in[3];
    const float* ln1_w    = (const float*)d_in[4];
    const float* router_W = (const float*)d_in[5];
    const float* router_b = (const float*)d_in[6];
    const float* Wq       = (const float*)d_in[7];
    const float* bq       = (const float*)d_in[8];
    const float* Wk       = (const float*)d_in[9];
    const float* bk       = (const float*)d_in[10];
    const float* Wv       = (const float*)d_in[11];
    const float* bv       = (const float*)d_in[12];
    const float* Wo       = (const float*)d_in[13];
    const float* bo       = (const float*)d_in[14];
    const float* alpha1   = (const float*)d_in[15];
    const float* alpha2   = (const float*)d_in[16];
    const float* ln2_w    = (const float*)d_in[17];
    const float* gate_w   = (const float*)d_in[18];
    const float* up_w     = (const float*)d_in[19];
    const float* down_w   = (const float*)d_in[20];
    const float* la_gA    = (const float*)d_in[21];
    const float* la_gB    = (const float*)d_in[22];
    const float* la_uA    = (const float*)d_in[23];
    const float* la_uB    = (const float*)d_in[24];
    const float* la_dA    = (const float*)d_in[25];
    const float* la_dB    = (const float*)d_in[26];
    float* out = (float*)d_out;

    float* pRrms  = sym<float>(&g_rrms);
    float* pXbar  = sym<float>(&g_xbar);
    float* pLog   = sym<float>(&g_logits);
    float* pGate  = sym<float>(&g_gate);
    float* pQ     = sym<float>(&g_Q);
    float* pK     = sym<float>(&g_K);
    float* pV     = sym<float>(&g_V);
    float* pS     = sym<float>(&g_S);
    float* pO     = sym<float>(&g_O);
    float* pT     = sym<float>(&g_T);
    float* pDelta = sym<float>(&g_delta);
    float* pX1    = sym<float>(&g_x1);
    float* pH     = sym<float>(&g_h);
    float* pG     = sym<float>(&g_G);
    float* pU     = sym<float>(&g_U);
    float* pLt    = sym<float>(&g_lt);

    const int EW_B = (MQ * DD + 255) / 256;

    // ---- router ----
    rowrms_k<<<MQ, 256>>>(x_q, pRrms, DD);
    xbar_k<<<(BB * DD + 255) / 256, 256>>>(x_q, pRrms, ln1_w, pXbar);
    router_logits_k<<<BB * 4, 256>>>(pXbar, router_W, router_b, pLog);
    gate_k<<<1, 32>>>(pLog, pGate);

    // ---- experts ----
    const float* zs[3]  = {z_a, z_v, z_av};
    const int    nks[3] = {512, 512, 1024};
    const float att_scale = 0.08838834764831843f;  // 1/sqrt(128)

    for (int e = 0; e < 3; e++) {
        const float* z = zs[e];
        int NK = nks[e];
        int MZ = BB * NK;

        // projections
        gemm(false, MQ, DD, DD, x_q, DD, 0, 0, Wq + (long long)e * DD * DD, DD, 0, 0,
             pQ, DD, 0, 0, 1, 1, 1.f, 0.f, bq + e * DD);
        gemm(false, MZ, DD, DD, z, DD, 0, 0, Wk + (long long)e * DD * DD, DD, 0, 0,
             pK, DD, 0, 0, 1, 1, 1.f, 0.f, bk + e * DD);
        gemm(false, MZ, DD, DD, z, DD, 0, 0, Wv + (long long)e * DD * DD, DD, 0, 0,
             pV, DD, 0, 0, 1, 1, 1.f, 0.f, bv + e * DD);

        // scores: per (b,h): [NQ, NK] = Q[b,:,h,:] @ K[b,:,h,:]^T * scale
        gemm(true, NQL, NK, DHH,
             pQ, DD, (long long)NQL * DD, DHH,
             pK, DD, (long long)NK * DD, DHH,
             pS, NK, (long long)HH * NQL * NK, (long long)NQL * NK,
             BB * HH, HH, att_scale, 0.f, nullptr);

        softmax_rows_k<<<BB * HH * NQL, 256>>>(pS, NK);

        // PV: per (b,h): [NQ, DH] = P @ V[b,:,h,:]
        gemm(false, NQL, DHH, NK,
             pS, NK, (long long)HH * NQL * NK, (long long)NQL * NK,
             pV, DD, (long long)NK * DD, DHH,
             pO, DD, (long long)NQL * DD, DHH,
             BB * HH, HH, 1.f, 0.f, nullptr);

        // out projection
        gemm(false, MQ, DD, DD, pO, DD, 0, 0, Wo + (long long)e * DD * DD, DD, 0, 0,
             pT, DD, 0, 0, 1, 1, 1.f, 0.f, bo + e * DD);

        adddelta_k<<<EW_B, 256>>>(pT, pGate, e, e == 0 ? 1 : 0, pDelta);
    }

    // ---- x1 = x_q + sigmoid(alpha1)*delta ----
    x1_k<<<EW_B, 256>>>(x_q, pDelta, alpha1, pX1);

    // ---- MLP with LoRA ----
    rmsnorm_k<<<MQ, 256>>>(pX1, ln2_w, pH, DD);

    // gate path
    gemm(false, MQ, FFD, DD, pH, DD, 0, 0, gate_w, FFD, 0, 0, pG, FFD, 0, 0, 1, 1, 1.f, 0.f, nullptr);
    gemm(false, MQ, RR, DD, pH, DD, 0, 0, la_gA, RR, 0, 0, pLt, RR, 0, 0, 1, 1, 1.f, 0.f, nullptr);
    gemm(false, MQ, FFD, RR, pLt, RR, 0, 0, la_gB, FFD, 0, 0, pG, FFD, 0, 0, 1, 1, LORA_SCALE, 1.f, nullptr);

    // up path
    gemm(false, MQ, FFD, DD, pH, DD, 0, 0, up_w, FFD, 0, 0, pU, FFD, 0, 0, 1, 1, 1.f, 0.f, nullptr);
    gemm(false, MQ, RR, DD, pH, DD, 0, 0, la_uA, RR, 0, 0, pLt, RR, 0, 0, 1, 1, 1.f, 0.f, nullptr);
    gemm(false, MQ, FFD, RR, pLt, RR, 0, 0, la_uB, FFD, 0, 0, pU, FFD, 0, 0, 1, 1, LORA_SCALE, 1.f, nullptr);

    // x_down = silu(gate) + up  (in place into pG)
    {
        long long n = (long long)MQ * FFD;
        int blocks = (int)((n + 255) / 256);
        silu_add_k<<<blocks, 256>>>(pG, pU, n);
    }

    // down path
    gemm(false, MQ, DD, FFD, pG, FFD, 0, 0, down_w, DD, 0, 0, pT, DD, 0, 0, 1, 1, 1.f, 0.f, nullptr);
    gemm(false, MQ, RR, FFD, pG, FFD, 0, 0, la_dA, RR, 0, 0, pLt, RR, 0, 0, 1, 1, 1.f, 0.f, nullptr);
    gemm(false, MQ, DD, RR, pLt, RR, 0, 0, la_dB, DD, 0, 0, pT, DD, 0, 0, 1, 1, LORA_SCALE, 1.f, nullptr);

    // out = x1 + sigmoid(alpha2)*mlp_out
    out_k<<<EW_B, 256>>>(pX1, pT, alpha2, out);
}

// round 3
// speedup vs baseline: 3.3323x; 3.3323x over previous
#include <cuda_runtime.h>
#include <math.h>

// ---------------------------------------------------------------------------
// Problem constants (from reference)
// ---------------------------------------------------------------------------
#define BB   8
#define NQL  1024
#define DD   2048
#define HH   16
#define DHH  128
#define FFD  8192
#define RR   16
#define MQ   (BB*NQL)          // 8192 rows of x_q
#define LORA_SCALE 1.0f

// ---------------------------------------------------------------------------
// Scratch (device globals; allocation-free rule)
// ---------------------------------------------------------------------------
__device__ __align__(256) float g_rrms[MQ];
__device__ __align__(256) float g_xbar[BB*DD];
__device__ __align__(256) float g_logits[BB*4];
__device__ __align__(256) float g_gate[BB*4];
__device__ __align__(256) float g_Q[(long long)MQ*DD];
__device__ __align__(256) float g_K[(long long)MQ*DD];
__device__ __align__(256) float g_V[(long long)MQ*DD];
__device__ __align__(256) float g_S[(long long)BB*HH*NQL*1024];   // scores, max NK=1024
__device__ __align__(256) float g_O[(long long)MQ*DD];
__device__ __align__(256) float g_T[(long long)MQ*DD];
__device__ __align__(256) float g_delta[(long long)MQ*DD];
__device__ __align__(256) float g_x1[(long long)MQ*DD];
__device__ __align__(256) float g_h[(long long)MQ*DD];
__device__ __align__(256) float g_G[(long long)MQ*FFD];
__device__ __align__(256) float g_U[(long long)MQ*FFD];
__device__ __align__(256) float g_lt[(long long)MQ*RR];

// ---------------------------------------------------------------------------
// tf32 helpers
// ---------------------------------------------------------------------------
__device__ __forceinline__ float cvt_tf32(float x)
{
    unsigned u;
    asm("cvt.rna.tf32.f32 %0, %1;" : "=r"(u) : "f"(x));
    return __uint_as_float(u);
}

__device__ __forceinline__ void mma_tf32(float& c0, float& c1, float& c2, float& c3,
                                         unsigned a0, unsigned a1, unsigned a2, unsigned a3,
                                         unsigned b0, unsigned b1)
{
    asm volatile(
        "mma.sync.aligned.m16n8k8.row.col.f32.tf32.tf32.f32 "
        "{%0,%1,%2,%3}, {%4,%5,%6,%7}, {%8,%9}, {%0,%1,%2,%3};"
        : "+f"(c0), "+f"(c1), "+f"(c2), "+f"(c3)
        : "r"(a0), "r"(a1), "r"(a2), "r"(a3), "r"(b0), "r"(b1));
}

// ---------------------------------------------------------------------------
// Tensor-core strided-batched GEMM: C = alpha * A*op(B) (+ bias) (+ beta*C)
// A: [M,K] row-major (lda). TB=0: B[K,N] row-major; TB=1: B stored [N,K] (B^T).
// Batch z: offset = (z/zdiv)*s1 + (z%zdiv)*s2 for A,B,C.
// Block 128x128x32, 256 threads = 8 warps (4 M x 2 N), warp tile 32x64.
// Requires: K % 16 == 0, N % 16 == 0, 16B-aligned bases, lda/ldb/ldc % 4 == 0.
// ---------------------------------------------------------------------------
template <int TB>
__global__ __launch_bounds__(256, 2)
void tfgemm_k(int M, int N, int K,
              const float* __restrict__ A, int lda, long long sA1, long long sA2,
              const float* __restrict__ B, int ldb, long long sB1, long long sB2,
              float* __restrict__ C, int ldc, long long sC1, long long sC2,
              int zdiv, float alpha, float beta, const float* __restrict__ bias)
{
    const int BM = 128, BN = 128, BK = 32;
    __shared__ float As[BM][BK + 4];   // [m][k], pad 4 -> conflict-free frag loads
    __shared__ float Bs[BK][BN + 8];   // [k][n], pad 8 -> conflict-free frag loads

    int z = blockIdx.z;
    A += (long long)(z / zdiv) * sA1 + (long long)(z % zdiv) * sA2;
    B += (long long)(z / zdiv) * sB1 + (long long)(z % zdiv) * sB2;
    C += (long long)(z / zdiv) * sC1 + (long long)(z % zdiv) * sC2;

    int bm = blockIdx.y * BM;
    int bn = blockIdx.x * BN;
    int tid  = threadIdx.x;
    int lane = tid & 31;
    int wid  = tid >> 5;
    int wm = (wid & 3) * 32;   // warp M offset in tile
    int wn = (wid >> 2) * 64;  // warp N offset in tile

    // accumulators: 2 m-tiles x 8 n-tiles x 4 regs
    float acc[2][8][4];
#pragma unroll
    for (int i = 0; i < 2; i++)
#pragma unroll
        for (int j = 0; j < 8; j++)
#pragma unroll
            for (int q = 0; q < 4; q++) acc[i][j][q] = 0.f;

    int ktiles = (K + BK - 1) / BK;
    for (int kt = 0; kt < ktiles; kt++) {
        int k0 = kt * BK;

        // ---- load A tile: 128 x 32 (2 threads per row, 16 k each) ----
        {
            int row = tid >> 1;
            int kb  = (tid & 1) * 16;
            int gm  = bm + row;
#pragma unroll
            for (int v = 0; v < 4; v++) {
                int kk = kb + v * 4;
                int gk = k0 + kk;
                float4 val = make_float4(0.f, 0.f, 0.f, 0.f);
                if (gm < M && gk < K)
                    val = *reinterpret_cast<const float4*>(A + (long long)gm * lda + gk);
                As[row][kk + 0] = cvt_tf32(val.x);
                As[row][kk + 1] = cvt_tf32(val.y);
                As[row][kk + 2] = cvt_tf32(val.z);
                As[row][kk + 3] = cvt_tf32(val.w);
            }
        }
        // ---- load B tile -> Bs[k][n] ----
        if (TB) {
            // B stored [N,K]; row n, 16 k per thread, transpose into Bs
            int n  = tid >> 1;
            int kb = (tid & 1) * 16;
            int gn = bn + n;
#pragma unroll
            for (int v = 0; v < 4; v++) {
                int kk = kb + v * 4;
                int gk = k0 + kk;
                float4 val = make_float4(0.f, 0.f, 0.f, 0.f);
                if (gn < N && gk < K)
                    val = *reinterpret_cast<const float4*>(B + (long long)gn * ldb + gk);
                Bs[kk + 0][n] = cvt_tf32(val.x);
                Bs[kk + 1][n] = cvt_tf32(val.y);
                Bs[kk + 2][n] = cvt_tf32(val.z);
                Bs[kk + 3][n] = cvt_tf32(val.w);
            }
        } else {
            // B [K,N] row-major; 8 threads per k-row, 16 n each
            int k  = tid >> 3;
            int nb = (tid & 7) * 16;
            int gk = k0 + k;
#pragma unroll
            for (int v = 0; v < 4; v++) {
                int nn = nb + v * 4;
                int gn = bn + nn;
                float4 val = make_float4(0.f, 0.f, 0.f, 0.f);
                if (gk < K && gn < N)
                    val = *reinterpret_cast<const float4*>(B + (long long)gk * ldb + gn);
                Bs[k][nn + 0] = cvt_tf32(val.x);
                Bs[k][nn + 1] = cvt_tf32(val.y);
                Bs[k][nn + 2] = cvt_tf32(val.z);
                Bs[k][nn + 3] = cvt_tf32(val.w);
            }
        }
        __syncthreads();

        // ---- compute: 4 k-steps of 8 ----
#pragma unroll
        for (int ks = 0; ks < 4; ks++) {
            int kk = ks * 8;
            int r  = (lane >> 2);
            int cA = kk + (lane & 3);

            unsigned afr[2][4];
#pragma unroll
            for (int mi = 0; mi < 2; mi++) {
                int r0 = wm + mi * 16 + r;
                afr[mi][0] = __float_as_uint(As[r0    ][cA    ]);
                afr[mi][1] = __float_as_uint(As[r0 + 8][cA    ]);
                afr[mi][2] = __float_as_uint(As[r0    ][cA + 4]);
                afr[mi][3] = __float_as_uint(As[r0 + 8][cA + 4]);
            }
            unsigned bfr[8][2];
#pragma unroll
            for (int ni = 0; ni < 8; ni++) {
                int n0 = wn + ni * 8 + r;
                bfr[ni][0] = __float_as_uint(Bs[kk + (lane & 3)    ][n0]);
                bfr[ni][1] = __float_as_uint(Bs[kk + (lane & 3) + 4][n0]);
            }
#pragma unroll
            for (int mi = 0; mi < 2; mi++)
#pragma unroll
                for (int ni = 0; ni < 8; ni++)
                    mma_tf32(acc[mi][ni][0], acc[mi][ni][1], acc[mi][ni][2], acc[mi][ni][3],
                             afr[mi][0], afr[mi][1], afr[mi][2], afr[mi][3],
                             bfr[ni][0], bfr[ni][1]);
        }
        __syncthreads();
    }

    // ---- epilogue ----
#pragma unroll
    for (int mi = 0; mi < 2; mi++) {
        int r0 = bm + wm + mi * 16 + (lane >> 2);
#pragma unroll
        for (int ni = 0; ni < 8; ni++) {
            int cbase = bn + wn + ni * 8 + 2 * (lane & 3);
#pragma unroll
            for (int q = 0; q < 4; q++) {
                int gm = r0 + ((q >> 1) ? 8 : 0);
                int gn = cbase + (q & 1);
                if (gm >= M || gn >= N) continue;
                float v = alpha * acc[mi][ni][q];
                if (bias) v += bias[gn];
                long long off = (long long)gm * ldc + gn;
                if (beta != 0.f) v += beta * C[off];
                C[off] = v;
            }
        }
    }
}

// ---------------------------------------------------------------------------
// Row helpers
// ---------------------------------------------------------------------------
__global__ void rowrms_k(const float* __restrict__ X, float* __restrict__ rrms, int ncols)
{
    int row = blockIdx.x;
    const float* p = X + (long long)row * ncols;
    __shared__ float red[256];
    float s = 0.f;
    for (int c = threadIdx.x; c < ncols; c += 256) { float v = p[c]; s += v * v; }
    red[threadIdx.x] = s; __syncthreads();
    for (int st = 128; st > 0; st >>= 1) {
        if (threadIdx.x < st) red[threadIdx.x] += red[threadIdx.x + st];
        __syncthreads();
    }
    if (threadIdx.x == 0) rrms[row] = rsqrtf(red[0] / ncols + 1e-6f);
}

__global__ void xbar_k(const float* __restrict__ X, const float* __restrict__ rrms,
                       const float* __restrict__ w, float* __restrict__ xbar)
{
    int idx = blockIdx.x * blockDim.x + threadIdx.x;
    if (idx >= BB * DD) return;
    int b = idx / DD, d = idx % DD;
    const float* xp = X + (long long)b * NQL * DD + d;
    const float* rp = rrms + b * NQL;
    float s = 0.f;
    for (int n = 0; n < NQL; n++) s += xp[(long long)n * DD] * rp[n];
    xbar[idx] = w[d] * s * (1.f / NQL);
}

__global__ void router_logits_k(const float* __restrict__ xbar, const float* __restrict__ W,
                                const float* __restrict__ bias, float* __restrict__ logits)
{
    int b = blockIdx.x >> 2, e = blockIdx.x & 3;
    __shared__ float red[256];
    float s = 0.f;
    for (int k = threadIdx.x; k < DD; k += 256) s += xbar[b * DD + k] * W[k * 4 + e];
    red[threadIdx.x] = s; __syncthreads();
    for (int st = 128; st > 0; st >>= 1) {
        if (threadIdx.x < st) red[threadIdx.x] += red[threadIdx.x + st];
        __syncthreads();
    }
    if (threadIdx.x == 0) logits[b * 4 + e] = red[0] + bias[e];
}

__global__ void gate_k(const float* __restrict__ logits, float* __restrict__ gate)
{
    int b = threadIdx.x;
    if (b >= BB) return;
    float l[4]; float mx = -1e30f;
    for (int e = 0; e < 4; e++) { l[e] = logits[b * 4 + e]; mx = fmaxf(mx, l[e]); }
    float s = 0.f;
    for (int e = 0; e < 4; e++) { l[e] = expf(l[e] - mx); s += l[e]; }
    for (int e = 0; e < 4; e++) l[e] /= s;
    int i1 = 0;
    for (int e = 1; e < 4; e++) if (l[e] > l[i1]) i1 = e;
    int i2 = -1;
    for (int e = 0; e < 4; e++) if (e != i1 && (i2 < 0 || l[e] > l[i2])) i2 = e;
    float denom = l[i1] + l[i2] + 1e-10f;
    float g[4] = {0.f, 0.f, 0.f, 0.f};
    g[i1] = l[i1] / denom;
    g[i2] = l[i2] / denom;
    for (int e = 0; e < 4; e++) gate[b * 4 + e] = g[e];
}

__global__ void softmax_rows_k(float* __restrict__ S, int ncols)
{
    int row = blockIdx.x;
    float* p = S + (long long)row * ncols;
    __shared__ float sm[1024];
    __shared__ float red[256];
    int tid = threadIdx.x;
    float mx = -1e30f;
    for (int c = tid; c < ncols; c += 256) { float v = p[c]; sm[c] = v; mx = fmaxf(mx, v); }
    red[tid] = mx; __syncthreads();
    for (int st = 128; st > 0; st >>= 1) {
        if (tid < st) red[tid] = fmaxf(red[tid], red[tid + st]);
        __syncthreads();
    }
    mx = red[0]; __syncthreads();
    float sum = 0.f;
    for (int c = tid; c < ncols; c += 256) { float e = __expf(sm[c] - mx); sm[c] = e; sum += e; }
    red[tid] = sum; __syncthreads();
    for (int st = 128; st > 0; st >>= 1) {
        if (tid < st) red[tid] += red[tid + st];
        __syncthreads();
    }
    float inv = 1.f / red[0];
    __syncthreads();
    for (int c = tid; c < ncols; c += 256) p[c] = sm[c] * inv;
}

__global__ void rmsnorm_k(const float* __restrict__ X, const float* __restrict__ w,
                          float* __restrict__ Y, int ncols)
{
    int row = blockIdx.x;
    const float* p = X + (long long)row * ncols;
    float* q = Y + (long long)row * ncols;
    __shared__ float red[256];
    float s = 0.f;
    for (int c = threadIdx.x; c < ncols; c += 256) { float v = p[c]; s += v * v; }
    red[threadIdx.x] = s; __syncthreads();
    for (int st = 128; st > 0; st >>= 1) {
        if (threadIdx.x < st) red[threadIdx.x] += red[threadIdx.x + st];
        __syncthreads();
    }
    float scale = rsqrtf(red[0] / ncols + 1e-6f);
    __syncthreads();
    for (int c = threadIdx.x; c < ncols; c += 256) q[c] = w[c] * p[c] * scale;
}

// ---------------------------------------------------------------------------
// Elementwise fusions
// ---------------------------------------------------------------------------
__global__ void adddelta_k(const float* __restrict__ T, const float* __restrict__ gate,
                           int e, int first, float* __restrict__ delta)
{
    int idx = blockIdx.x * blockDim.x + threadIdx.x;
    if (idx >= MQ * DD) return;
    int b = idx >> 21;
    float g = gate[b * 4 + e];
    float v = g * T[idx];
    delta[idx] = first ? v : (delta[idx] + v);
}

__global__ void x1_k(const float* __restrict__ xq, const float* __restrict__ delta,
                     const float* __restrict__ alpha1, float* __restrict__ x1)
{
    int idx = blockIdx.x * blockDim.x + threadIdx.x;
    if (idx >= MQ * DD) return;
    float s = 1.f / (1.f + expf(-alpha1[0]));
    x1[idx] = xq[idx] + s * delta[idx];
}

__global__ void silu_add_k(float* __restrict__ G, const float* __restrict__ U, long long n)
{
    long long idx = (long long)blockIdx.x * blockDim.x + threadIdx.x;
    if (idx >= n) return;
    float g = G[idx];
    G[idx] = g / (1.f + expf(-g)) + U[idx];
}

__global__ void out_k(const float* __restrict__ x1, const float* __restrict__ T,
                      const float* __restrict__ alpha2, float* __restrict__ out)
{
    int idx = blockIdx.x * blockDim.x + threadIdx.x;
    if (idx >= MQ * DD) return;
    float s = 1.f / (1.f + expf(-alpha2[0]));
    out[idx] = x1[idx] + s * T[idx];
}

// ---------------------------------------------------------------------------
// Host-side GEMM launcher
// ---------------------------------------------------------------------------
static void gemm(bool transB, int M, int N, int K,
                 const float* A, int lda, long long sA1, long long sA2,
                 const float* B, int ldb, long long sB1, long long sB2,
                 float* C, int ldc, long long sC1, long long sC2,
                 int Z, int zdiv, float alpha, float beta, const float* bias)
{
    dim3 grid((N + 127) / 128, (M + 127) / 128, Z);
    if (transB)
        tfgemm_k<1><<<grid, 256>>>(M, N, K, A, lda, sA1, sA2, B, ldb, sB1, sB2,
                                   C, ldc, sC1, sC2, zdiv, alpha, beta, bias);
    else
        tfgemm_k<0><<<grid, 256>>>(M, N, K, A, lda, sA1, sA2, B, ldb, sB1, sB2,
                                   C, ldc, sC1, sC2, zdiv, alpha, beta, bias);
}

template <typename T>
static T* sym(const void* s)
{
    void* p = nullptr;
    cudaGetSymbolAddress(&p, (const void*)s);
    return (T*)p;
}

// ---------------------------------------------------------------------------
// kernel_launch
// ---------------------------------------------------------------------------
extern "C" void kernel_launch(void* const* d_in, const int* in_sizes, int n_in,
                              void* d_out, int out_size)
{
    const float* x_q      = (const float*)d_in[0];
    const float* z_a      = (const float*)d_in[1];
    const float* z_v      = (const float*)d_in[2];
    const float* z_av     = (const float*)d_in[3];
    const float* ln1_w    = (const float*)d_in[4];
    const float* router_W = (const float*)d_in[5];
    const float* router_b = (const float*)d_in[6];
    const float* Wq       = (const float*)d_in[7];
    const float* bq       = (const float*)d_in[8];
    const float* Wk       = (const float*)d_in[9];
    const float* bk       = (const float*)d_in[10];
    const float* Wv       = (const float*)d_in[11];
    const float* bv       = (const float*)d_in[12];
    const float* Wo       = (const float*)d_in[13];
    const float* bo       = (const float*)d_in[14];
    const float* alpha1   = (const float*)d_in[15];
    const float* alpha2   = (const float*)d_in[16];
    const float* ln2_w    = (const float*)d_in[17];
    const float* gate_w   = (const float*)d_in[18];
    const float* up_w     = (const float*)d_in[19];
    const float* down_w   = (const float*)d_in[20];
    const float* la_gA    = (const float*)d_in[21];
    const float* la_gB    = (const float*)d_in[22];
    const float* la_uA    = (const float*)d_in[23];
    const float* la_uB    = (const float*)d_in[24];
    const float* la_dA    = (const float*)d_in[25];
    const float* la_dB    = (const float*)d_in[26];
    float* out = (float*)d_out;

    float* pRrms  = sym<float>(&g_rrms);
    float* pXbar  = sym<float>(&g_xbar);
    float* pLog   = sym<float>(&g_logits);
    float* pGate  = sym<float>(&g_gate);
    float* pQ     = sym<float>(&g_Q);
    float* pK     = sym<float>(&g_K);
    float* pV     = sym<float>(&g_V);
    float* pS     = sym<float>(&g_S);
    float* pO     = sym<float>(&g_O);
    float* pT     = sym<float>(&g_T);
    float* pDelta = sym<float>(&g_delta);
    float* pX1    = sym<float>(&g_x1);
    float* pH     = sym<float>(&g_h);
    float* pG     = sym<float>(&g_G);
    float* pU     = sym<float>(&g_U);
    float* pLt    = sym<float>(&g_lt);

    const int EW_B = (MQ * DD + 255) / 256;

    // ---- router ----
    rowrms_k<<<MQ, 256>>>(x_q, pRrms, DD);
    xbar_k<<<(BB * DD + 255) / 256, 256>>>(x_q, pRrms, ln1_w, pXbar);
    router_logits_k<<<BB * 4, 256>>>(pXbar, router_W, router_b, pLog);
    gate_k<<<1, 32>>>(pLog, pGate);

    // ---- experts ----
    const float* zs[3]  = {z_a, z_v, z_av};
    const int    nks[3] = {512, 512, 1024};
    const float att_scale = 0.08838834764831843f;  // 1/sqrt(128)

    for (int e = 0; e < 3; e++) {
        const float* z = zs[e];
        int NK = nks[e];
        int MZ = BB * NK;

        gemm(false, MQ, DD, DD, x_q, DD, 0, 0, Wq + (long long)e * DD * DD, DD, 0, 0,
             pQ, DD, 0, 0, 1, 1, 1.f, 0.f, bq + e * DD);
        gemm(false, MZ, DD, DD, z, DD, 0, 0, Wk + (long long)e * DD * DD, DD, 0, 0,
             pK, DD, 0, 0, 1, 1, 1.f, 0.f, bk + e * DD);
        gemm(false, MZ, DD, DD, z, DD, 0, 0, Wv + (long long)e * DD * DD, DD, 0, 0,
             pV, DD, 0, 0, 1, 1, 1.f, 0.f, bv + e * DD);

        // scores: per (b,h): [NQ, NK] = Q[b,:,h,:] @ K[b,:,h,:]^T * scale
        gemm(true, NQL, NK, DHH,
             pQ, DD, (long long)NQL * DD, DHH,
             pK, DD, (long long)NK * DD, DHH,
             pS, NK, (long long)HH * NQL * NK, (long long)NQL * NK,
             BB * HH, HH, att_scale, 0.f, nullptr);

        softmax_rows_k<<<BB * HH * NQL, 256>>>(pS, NK);

        // PV: per (b,h): [NQ, DH] = P @ V[b,:,h,:]
        gemm(false, NQL, DHH, NK,
             pS, NK, (long long)HH * NQL * NK, (long long)NQL * NK,
             pV, DD, (long long)NK * DD, DHH,
             pO, DD, (long long)NQL * DD, DHH,
             BB * HH, HH, 1.f, 0.f, nullptr);

        gemm(false, MQ, DD, DD, pO, DD, 0, 0, Wo + (long long)e * DD * DD, DD, 0, 0,
             pT, DD, 0, 0, 1, 1, 1.f, 0.f, bo + e * DD);

        adddelta_k<<<EW_B, 256>>>(pT, pGate, e, e == 0 ? 1 : 0, pDelta);
    }

    // ---- x1 = x_q + sigmoid(alpha1)*delta ----
    x1_k<<<EW_B, 256>>>(x_q, pDelta, alpha1, pX1);

    // ---- MLP with LoRA ----
    rmsnorm_k<<<MQ, 256>>>(pX1, ln2_w, pH, DD);

    // gate path
    gemm(false, MQ, FFD, DD, pH, DD, 0, 0, gate_w, FFD, 0, 0, pG, FFD, 0, 0, 1, 1, 1.f, 0.f, nullptr);
    gemm(false, MQ, RR, DD, pH, DD, 0, 0, la_gA, RR, 0, 0, pLt, RR, 0, 0, 1, 1, 1.f, 0.f, nullptr);
    gemm(false, MQ, FFD, RR, pLt, RR, 0, 0, la_gB, FFD, 0, 0, pG, FFD, 0, 0, 1, 1, LORA_SCALE, 1.f, nullptr);

    // up path
    gemm(false, MQ, FFD, DD, pH, DD, 0, 0, up_w, FFD, 0, 0, pU, FFD, 0, 0, 1, 1, 1.f, 0.f, nullptr);
    gemm(false, MQ, RR, DD, pH, DD, 0, 0, la_uA, RR, 0, 0, pLt, RR, 0, 0, 1, 1, 1.f, 0.f, nullptr);
    gemm(false, MQ, FFD, RR, pLt, RR, 0, 0, la_uB, FFD, 0, 0, pU, FFD, 0, 0, 1, 1, LORA_SCALE, 1.f, nullptr);

    // x_down = silu(gate) + up  (in place into pG)
    {
        long long n = (long long)MQ * FFD;
        int blocks = (int)((n + 255) / 256);
        silu_add_k<<<blocks, 256>>>(pG, pU, n);
    }

    // down path
    gemm(false, MQ, DD, FFD, pG, FFD, 0, 0, down_w, DD, 0, 0, pT, DD, 0, 0, 1, 1, 1.f, 0.f, nullptr);
    gemm(false, MQ, RR, FFD, pG, FFD, 0, 0, la_dA, RR, 0, 0, pLt, RR, 0, 0, 1, 1, 1.f, 0.f, nullptr);
    gemm(false, MQ, DD, RR, pLt, RR, 0, 0, la_dB, DD, 0, 0, pT, DD, 0, 0, 1, 1, LORA_SCALE, 1.f, nullptr);

    // out = x1 + sigmoid(alpha2)*mlp_out
    out_k<<<EW_B, 256>>>(pX1, pT, alpha2, out);
}

// round 4
// speedup vs baseline: 4.9750x; 1.4930x over previous
#include <cuda_runtime.h>
#include <math.h>

// ---------------------------------------------------------------------------
// Problem constants
// ---------------------------------------------------------------------------
#define BB   8
#define NQL  1024
#define DD   2048
#define HH   16
#define DHH  128
#define FFD  8192
#define RR   16
#define MQ   (BB*NQL)
#define LORA_SCALE 1.0f

// ---------------------------------------------------------------------------
// Scratch (device globals)
// ---------------------------------------------------------------------------
__device__ __align__(256) float g_rrms[MQ];
__device__ __align__(256) float g_xbar[BB*DD];
__device__ __align__(256) float g_logits[BB*4];
__device__ __align__(256) float g_gate[BB*4];
__device__ __align__(256) float g_Q[(long long)MQ*DD];
__device__ __align__(256) float g_K[(long long)MQ*DD];
__device__ __align__(256) float g_V[(long long)MQ*DD];
__device__ __align__(256) float g_S[(long long)BB*HH*NQL*1024];
__device__ __align__(256) float g_O[(long long)MQ*DD];
__device__ __align__(256) float g_T[(long long)MQ*DD];
__device__ __align__(256) float g_delta[(long long)MQ*DD];
__device__ __align__(256) float g_x1[(long long)MQ*DD];
__device__ __align__(256) float g_h[(long long)MQ*DD];
__device__ __align__(256) float g_G[(long long)MQ*FFD];
__device__ __align__(256) float g_U[(long long)MQ*FFD];
__device__ __align__(256) float g_lt[(long long)MQ*RR];

// ---------------------------------------------------------------------------
// tf32 / cp.async helpers
// ---------------------------------------------------------------------------
__device__ __forceinline__ unsigned cvt_tf32_u(float x)
{
    unsigned u;
    asm("cvt.rna.tf32.f32 %0, %1;" : "=r"(u) : "f"(x));
    return u;
}

__device__ __forceinline__ void mma_tf32(float& c0, float& c1, float& c2, float& c3,
                                         unsigned a0, unsigned a1, unsigned a2, unsigned a3,
                                         unsigned b0, unsigned b1)
{
    asm volatile(
        "mma.sync.aligned.m16n8k8.row.col.f32.tf32.tf32.f32 "
        "{%0,%1,%2,%3}, {%4,%5,%6,%7}, {%8,%9}, {%0,%1,%2,%3};"
        : "+f"(c0), "+f"(c1), "+f"(c2), "+f"(c3)
        : "r"(a0), "r"(a1), "r"(a2), "r"(a3), "r"(b0), "r"(b1));
}

__device__ __forceinline__ void cp16(float* dst_smem, const float* src, bool pred)
{
    unsigned d = (unsigned)__cvta_generic_to_shared(dst_smem);
    int sz = pred ? 16 : 0;
    asm volatile("cp.async.cg.shared.global [%0], [%1], 16, %2;\n"
                 :: "r"(d), "l"(src), "r"(sz));
}
__device__ __forceinline__ void cp_commit() { asm volatile("cp.async.commit_group;\n"); }
template <int N>
__device__ __forceinline__ void cp_wait() { asm volatile("cp.async.wait_group %0;\n" :: "n"(N)); }

// ---------------------------------------------------------------------------
// Pipelined tf32 tensor-core strided-batched GEMM.
// C = rowscale * (alpha * A*op(B) + bias) + beta*C
// A: [M,K] row-major. TB=0: B[K,N] row-major; TB=1: B stored [N,K] (used as B^T).
// Batch z: offset = (z/zdiv)*s1 + (z%zdiv)*s2.
// Block 128x128x32 double-buffered cp.async; 8 warps (4Mx2N), warp tile 32x64.
// Requires: K%16==0, N%4==0, M%128==0 (or guard ok), 16B-aligned bases, ld%4==0.
// ---------------------------------------------------------------------------
#define A_STRIDE 36
#define A_STAGE  (128*A_STRIDE)     // 4608 floats
#define B0_STRIDE 136
#define B0_STAGE (32*B0_STRIDE)     // 4352 floats
#define B1_STRIDE 36
#define B1_STAGE (128*B1_STRIDE)    // 4608 floats
#define SMEM_FLOATS (2*A_STAGE + 2*B1_STAGE)   // 18432 floats = 73728 B (max)
#define SMEM_BYTES (SMEM_FLOATS*4)

template <int TB>
__global__ __launch_bounds__(256, 2)
void tfgemm_k(int M, int N, int K,
              const float* __restrict__ A, int lda, long long sA1, long long sA2,
              const float* __restrict__ B, int ldb, long long sB1, long long sB2,
              float* __restrict__ C, int ldc, long long sC1, long long sC2,
              int zdiv, float alpha, float beta, const float* __restrict__ bias,
              const float* __restrict__ rowscale, int rs_shift, int rs_mul, int rs_off)
{
    extern __shared__ float smem[];
    float* As = smem;                    // [2][128][36]
    float* Bs = smem + 2 * A_STAGE;      // TB0: [2][32][136]; TB1: [2][128][36]

    int z = blockIdx.z;
    A += (long long)(z / zdiv) * sA1 + (long long)(z % zdiv) * sA2;
    B += (long long)(z / zdiv) * sB1 + (long long)(z % zdiv) * sB2;
    C += (long long)(z / zdiv) * sC1 + (long long)(z % zdiv) * sC2;

    const int BK = 32;
    int bm = blockIdx.y * 128;
    int bn = blockIdx.x * 128;
    int tid  = threadIdx.x;
    int lane = tid & 31;
    int wid  = tid >> 5;
    int wm = (wid & 3) * 32;
    int wn = (wid >> 2) * 64;

    float acc[2][8][4];
#pragma unroll
    for (int i = 0; i < 2; i++)
#pragma unroll
        for (int j = 0; j < 8; j++)
#pragma unroll
            for (int q = 0; q < 4; q++) acc[i][j][q] = 0.f;

    int ktiles = (K + BK - 1) / BK;

    // ---- tile loader (cp.async) ----
    auto load_tile = [&](int kt, int stage) {
        int k0 = kt * BK;
        // A: 128 rows x 32 k = 1024 float4
#pragma unroll
        for (int i = 0; i < 4; i++) {
            int idx = tid + i * 256;
            int row = idx >> 3;
            int kq  = (idx & 7) * 4;
            int gm  = bm + row;
            bool p  = (gm < M) && (k0 + kq < K);
            cp16(&As[stage * A_STAGE + row * A_STRIDE + kq],
                 A + (long long)gm * lda + k0 + kq, p);
        }
        if (TB) {
            // B [N,K]: 128 n-rows x 32 k
#pragma unroll
            for (int i = 0; i < 4; i++) {
                int idx = tid + i * 256;
                int n  = idx >> 3;
                int kq = (idx & 7) * 4;
                int gn = bn + n;
                bool p = (gn < N) && (k0 + kq < K);
                cp16(&Bs[stage * B1_STAGE + n * B1_STRIDE + kq],
                     B + (long long)gn * ldb + k0 + kq, p);
            }
        } else {
            // B [K,N]: 32 k-rows x 128 n
#pragma unroll
            for (int i = 0; i < 4; i++) {
                int idx = tid + i * 256;
                int k  = idx >> 5;
                int nq = (idx & 31) * 4;
                int gk = k0 + k;
                bool p = (gk < K) && (bn + nq < N);
                cp16(&Bs[stage * B0_STAGE + k * B0_STRIDE + nq],
                     B + (long long)gk * ldb + bn + nq, p);
            }
        }
        cp_commit();
    };

    load_tile(0, 0);

    for (int kt = 0; kt < ktiles; kt++) {
        int cur = kt & 1;
        if (kt + 1 < ktiles) {
            load_tile(kt + 1, (kt + 1) & 1);
            cp_wait<1>();
        } else {
            cp_wait<0>();
        }
        __syncthreads();

        const float* As_f = As + cur * A_STAGE;
        const float* Bs_f = Bs + cur * (TB ? B1_STAGE : B0_STAGE);
        int r  = lane >> 2;
        int kq = lane & 3;

#pragma unroll
        for (int ks = 0; ks < 4; ks++) {
            int kk = ks * 8;
            unsigned afr[2][4];
#pragma unroll
            for (int mi = 0; mi < 2; mi++) {
                int r0 = wm + mi * 16 + r;
                afr[mi][0] = cvt_tf32_u(As_f[(r0    ) * A_STRIDE + kk + kq    ]);
                afr[mi][1] = cvt_tf32_u(As_f[(r0 + 8) * A_STRIDE + kk + kq    ]);
                afr[mi][2] = cvt_tf32_u(As_f[(r0    ) * A_STRIDE + kk + kq + 4]);
                afr[mi][3] = cvt_tf32_u(As_f[(r0 + 8) * A_STRIDE + kk + kq + 4]);
            }
            unsigned bfr[8][2];
#pragma unroll
            for (int ni = 0; ni < 8; ni++) {
                int n0 = wn + ni * 8 + r;
                if (TB) {
                    bfr[ni][0] = cvt_tf32_u(Bs_f[n0 * B1_STRIDE + kk + kq    ]);
                    bfr[ni][1] = cvt_tf32_u(Bs_f[n0 * B1_STRIDE + kk + kq + 4]);
                } else {
                    bfr[ni][0] = cvt_tf32_u(Bs_f[(kk + kq    ) * B0_STRIDE + n0]);
                    bfr[ni][1] = cvt_tf32_u(Bs_f[(kk + kq + 4) * B0_STRIDE + n0]);
                }
            }
#pragma unroll
            for (int mi = 0; mi < 2; mi++)
#pragma unroll
                for (int ni = 0; ni < 8; ni++)
                    mma_tf32(acc[mi][ni][0], acc[mi][ni][1], acc[mi][ni][2], acc[mi][ni][3],
                             afr[mi][0], afr[mi][1], afr[mi][2], afr[mi][3],
                             bfr[ni][0], bfr[ni][1]);
        }
        __syncthreads();
    }

    // ---- epilogue ----
#pragma unroll
    for (int mi = 0; mi < 2; mi++) {
        int r0 = bm + wm + mi * 16 + (lane >> 2);
#pragma unroll
        for (int ni = 0; ni < 8; ni++) {
            int cbase = bn + wn + ni * 8 + 2 * (lane & 3);
#pragma unroll
            for (int q = 0; q < 4; q++) {
                int gm = r0 + ((q >> 1) ? 8 : 0);
                int gn = cbase + (q & 1);
                if (gm >= M || gn >= N) continue;
                float v = alpha * acc[mi][ni][q];
                if (bias) v += bias[gn];
                if (rowscale) v *= rowscale[(gm >> rs_shift) * rs_mul + rs_off];
                long long off = (long long)gm * ldc + gn;
                if (beta != 0.f) v += beta * C[off];
                C[off] = v;
            }
        }
    }
}

// ---------------------------------------------------------------------------
// Row helpers
// ---------------------------------------------------------------------------
__global__ void rowrms_k(const float* __restrict__ X, float* __restrict__ rrms, int ncols)
{
    int row = blockIdx.x;
    const float* p = X + (long long)row * ncols;
    __shared__ float red[256];
    float s = 0.f;
    for (int c = threadIdx.x; c < ncols; c += 256) { float v = p[c]; s += v * v; }
    red[threadIdx.x] = s; __syncthreads();
    for (int st = 128; st > 0; st >>= 1) {
        if (threadIdx.x < st) red[threadIdx.x] += red[threadIdx.x + st];
        __syncthreads();
    }
    if (threadIdx.x == 0) rrms[row] = rsqrtf(red[0] / ncols + 1e-6f);
}

__global__ void xbar_k(const float* __restrict__ X, const float* __restrict__ rrms,
                       const float* __restrict__ w, float* __restrict__ xbar)
{
    int idx = blockIdx.x * blockDim.x + threadIdx.x;
    if (idx >= BB * DD) return;
    int b = idx / DD, d = idx % DD;
    const float* xp = X + (long long)b * NQL * DD + d;
    const float* rp = rrms + b * NQL;
    float s = 0.f;
    for (int n = 0; n < NQL; n++) s += xp[(long long)n * DD] * rp[n];
    xbar[idx] = w[d] * s * (1.f / NQL);
}

__global__ void router_logits_k(const float* __restrict__ xbar, const float* __restrict__ W,
                                const float* __restrict__ bias, float* __restrict__ logits)
{
    int b = blockIdx.x >> 2, e = blockIdx.x & 3;
    __shared__ float red[256];
    float s = 0.f;
    for (int k = threadIdx.x; k < DD; k += 256) s += xbar[b * DD + k] * W[k * 4 + e];
    red[threadIdx.x] = s; __syncthreads();
    for (int st = 128; st > 0; st >>= 1) {
        if (threadIdx.x < st) red[threadIdx.x] += red[threadIdx.x + st];
        __syncthreads();
    }
    if (threadIdx.x == 0) logits[b * 4 + e] = red[0] + bias[e];
}

__global__ void gate_k(const float* __restrict__ logits, float* __restrict__ gate)
{
    int b = threadIdx.x;
    if (b >= BB) return;
    float l[4]; float mx = -1e30f;
    for (int e = 0; e < 4; e++) { l[e] = logits[b * 4 + e]; mx = fmaxf(mx, l[e]); }
    float s = 0.f;
    for (int e = 0; e < 4; e++) { l[e] = expf(l[e] - mx); s += l[e]; }
    for (int e = 0; e < 4; e++) l[e] /= s;
    int i1 = 0;
    for (int e = 1; e < 4; e++) if (l[e] > l[i1]) i1 = e;
    int i2 = -1;
    for (int e = 0; e < 4; e++) if (e != i1 && (i2 < 0 || l[e] > l[i2])) i2 = e;
    float denom = l[i1] + l[i2] + 1e-10f;
    float g[4] = {0.f, 0.f, 0.f, 0.f};
    g[i1] = l[i1] / denom;
    g[i2] = l[i2] / denom;
    for (int e = 0; e < 4; e++) gate[b * 4 + e] = g[e];
}

__global__ void softmax_rows_k(float* __restrict__ S, int ncols)
{
    int row = blockIdx.x;
    float* p = S + (long long)row * ncols;
    __shared__ float sm[1024];
    __shared__ float red[256];
    int tid = threadIdx.x;
    float mx = -1e30f;
    for (int c = tid; c < ncols; c += 256) { float v = p[c]; sm[c] = v; mx = fmaxf(mx, v); }
    red[tid] = mx; __syncthreads();
    for (int st = 128; st > 0; st >>= 1) {
        if (tid < st) red[tid] = fmaxf(red[tid], red[tid + st]);
        __syncthreads();
    }
    mx = red[0]; __syncthreads();
    float sum = 0.f;
    for (int c = tid; c < ncols; c += 256) { float e = __expf(sm[c] - mx); sm[c] = e; sum += e; }
    red[tid] = sum; __syncthreads();
    for (int st = 128; st > 0; st >>= 1) {
        if (tid < st) red[tid] += red[tid + st];
        __syncthreads();
    }
    float inv = 1.f / red[0];
    __syncthreads();
    for (int c = tid; c < ncols; c += 256) p[c] = sm[c] * inv;
}

__global__ void rmsnorm_k(const float* __restrict__ X, const float* __restrict__ w,
                          float* __restrict__ Y, int ncols)
{
    int row = blockIdx.x;
    const float* p = X + (long long)row * ncols;
    float* q = Y + (long long)row * ncols;
    __shared__ float red[256];
    float s = 0.f;
    for (int c = threadIdx.x; c < ncols; c += 256) { float v = p[c]; s += v * v; }
    red[threadIdx.x] = s; __syncthreads();
    for (int st = 128; st > 0; st >>= 1) {
        if (threadIdx.x < st) red[threadIdx.x] += red[threadIdx.x + st];
        __syncthreads();
    }
    float scale = rsqrtf(red[0] / ncols + 1e-6f);
    __syncthreads();
    for (int c = threadIdx.x; c < ncols; c += 256) q[c] = w[c] * p[c] * scale;
}

// ---------------------------------------------------------------------------
// Elementwise fusions
// ---------------------------------------------------------------------------
__global__ void x1_k(const float* __restrict__ xq, const float* __restrict__ delta,
                     const float* __restrict__ alpha1, float* __restrict__ x1)
{
    int idx = blockIdx.x * blockDim.x + threadIdx.x;
    if (idx >= MQ * DD) return;
    float s = 1.f / (1.f + expf(-alpha1[0]));
    x1[idx] = xq[idx] + s * delta[idx];
}

__global__ void silu_add_k(float* __restrict__ G, const float* __restrict__ U, long long n)
{
    long long idx = (long long)blockIdx.x * blockDim.x + threadIdx.x;
    if (idx >= n) return;
    float g = G[idx];
    G[idx] = g / (1.f + expf(-g)) + U[idx];
}

__global__ void out_k(const float* __restrict__ x1, const float* __restrict__ T,
                      const float* __restrict__ alpha2, float* __restrict__ out)
{
    int idx = blockIdx.x * blockDim.x + threadIdx.x;
    if (idx >= MQ * DD) return;
    float s = 1.f / (1.f + expf(-alpha2[0]));
    out[idx] = x1[idx] + s * T[idx];
}

// ---------------------------------------------------------------------------
// Host-side GEMM launcher
// ---------------------------------------------------------------------------
static void gemm(bool transB, int M, int N, int K,
                 const float* A, int lda, long long sA1, long long sA2,
                 const float* B, int ldb, long long sB1, long long sB2,
                 float* C, int ldc, long long sC1, long long sC2,
                 int Z, int zdiv, float alpha, float beta, const float* bias,
                 const float* rowscale = nullptr, int rs_shift = 0, int rs_mul = 0, int rs_off = 0)
{
    dim3 grid((N + 127) / 128, (M + 127) / 128, Z);
    if (transB)
        tfgemm_k<1><<<grid, 256, SMEM_BYTES>>>(M, N, K, A, lda, sA1, sA2, B, ldb, sB1, sB2,
                                               C, ldc, sC1, sC2, zdiv, alpha, beta, bias,
                                               rowscale, rs_shift, rs_mul, rs_off);
    else
        tfgemm_k<0><<<grid, 256, SMEM_BYTES>>>(M, N, K, A, lda, sA1, sA2, B, ldb, sB1, sB2,
                                               C, ldc, sC1, sC2, zdiv, alpha, beta, bias,
                                               rowscale, rs_shift, rs_mul, rs_off);
}

template <typename T>
static T* sym(const void* s)
{
    void* p = nullptr;
    cudaGetSymbolAddress(&p, (const void*)s);
    return (T*)p;
}

// ---------------------------------------------------------------------------
// kernel_launch
// ---------------------------------------------------------------------------
extern "C" void kernel_launch(void* const* d_in, const int* in_sizes, int n_in,
                              void* d_out, int out_size)
{
    const float* x_q      = (const float*)d_in[0];
    const float* z_a      = (const float*)d_in[1];
    const float* z_v      = (const float*)d_in[2];
    const float* z_av     = (const float*)d_in[3];
    const float* ln1_w    = (const float*)d_in[4];
    const float* router_W = (const float*)d_in[5];
    const float* router_b = (const float*)d_in[6];
    const float* Wq       = (const float*)d_in[7];
    const float* bq       = (const float*)d_in[8];
    const float* Wk       = (const float*)d_in[9];
    const float* bk       = (const float*)d_in[10];
    const float* Wv       = (const float*)d_in[11];
    const float* bv       = (const float*)d_in[12];
    const float* Wo       = (const float*)d_in[13];
    const float* bo       = (const float*)d_in[14];
    const float* alpha1   = (const float*)d_in[15];
    const float* alpha2   = (const float*)d_in[16];
    const float* ln2_w    = (const float*)d_in[17];
    const float* gate_w   = (const float*)d_in[18];
    const float* up_w     = (const float*)d_in[19];
    const float* down_w   = (const float*)d_in[20];
    const float* la_gA    = (const float*)d_in[21];
    const float* la_gB    = (const float*)d_in[22];
    const float* la_uA    = (const float*)d_in[23];
    const float* la_uB    = (const float*)d_in[24];
    const float* la_dA    = (const float*)d_in[25];
    const float* la_dB    = (const float*)d_in[26];
    float* out = (float*)d_out;

    // allow 72KB dynamic smem (once per call; idempotent, not a stream op)
    cudaFuncSetAttribute(tfgemm_k<0>, cudaFuncAttributeMaxDynamicSharedMemorySize, SMEM_BYTES);
    cudaFuncSetAttribute(tfgemm_k<1>, cudaFuncAttributeMaxDynamicSharedMemorySize, SMEM_BYTES);

    float* pRrms  = sym<float>(&g_rrms);
    float* pXbar  = sym<float>(&g_xbar);
    float* pLog   = sym<float>(&g_logits);
    float* pGate  = sym<float>(&g_gate);
    float* pQ     = sym<float>(&g_Q);
    float* pK     = sym<float>(&g_K);
    float* pV     = sym<float>(&g_V);
    float* pS     = sym<float>(&g_S);
    float* pO     = sym<float>(&g_O);
    float* pT     = sym<float>(&g_T);
    float* pDelta = sym<float>(&g_delta);
    float* pX1    = sym<float>(&g_x1);
    float* pH     = sym<float>(&g_h);
    float* pG     = sym<float>(&g_G);
    float* pU     = sym<float>(&g_U);
    float* pLt    = sym<float>(&g_lt);

    const int EW_B = (MQ * DD + 255) / 256;

    // ---- router ----
    rowrms_k<<<MQ, 256>>>(x_q, pRrms, DD);
    xbar_k<<<(BB * DD + 255) / 256, 256>>>(x_q, pRrms, ln1_w, pXbar);
    router_logits_k<<<BB * 4, 256>>>(pXbar, router_W, router_b, pLog);
    gate_k<<<1, 32>>>(pLog, pGate);

    // ---- experts ----
    const float* zs[3]  = {z_a, z_v, z_av};
    const int    nks[3] = {512, 512, 1024};
    const float att_scale = 0.08838834764831843f;  // 1/sqrt(128)

    for (int e = 0; e < 3; e++) {
        const float* z = zs[e];
        int NK = nks[e];
        int MZ = BB * NK;

        gemm(false, MQ, DD, DD, x_q, DD, 0, 0, Wq + (long long)e * DD * DD, DD, 0, 0,
             pQ, DD, 0, 0, 1, 1, 1.f, 0.f, bq + e * DD);
        gemm(false, MZ, DD, DD, z, DD, 0, 0, Wk + (long long)e * DD * DD, DD, 0, 0,
             pK, DD, 0, 0, 1, 1, 1.f, 0.f, bk + e * DD);
        gemm(false, MZ, DD, DD, z, DD, 0, 0, Wv + (long long)e * DD * DD, DD, 0, 0,
             pV, DD, 0, 0, 1, 1, 1.f, 0.f, bv + e * DD);

        // scores: per (b,h): [NQ, NK] = Q[b,:,h,:] @ K[b,:,h,:]^T * scale
        gemm(true, NQL, NK, DHH,
             pQ, DD, (long long)NQL * DD, DHH,
             pK, DD, (long long)NK * DD, DHH,
             pS, NK, (long long)HH * NQL * NK, (long long)NQL * NK,
             BB * HH, HH, att_scale, 0.f, nullptr);

        softmax_rows_k<<<BB * HH * NQL, 256>>>(pS, NK);

        // PV: per (b,h): [NQ, DH] = P @ V[b,:,h,:]
        gemm(false, NQL, DHH, NK,
             pS, NK, (long long)HH * NQL * NK, (long long)NQL * NK,
             pV, DD, (long long)NK * DD, DHH,
             pO, DD, (long long)NQL * DD, DHH,
             BB * HH, HH, 1.f, 0.f, nullptr);

        // out projection fused with gate-weighted delta accumulation:
        // delta (+)= gate[b,e] * (O @ Wo[e] + bo[e])
        gemm(false, MQ, DD, DD, pO, DD, 0, 0, Wo + (long long)e * DD * DD, DD, 0, 0,
             pDelta, DD, 0, 0, 1, 1, 1.f, (e == 0) ? 0.f : 1.f, bo + e * DD,
             pGate, 10, 4, e);
    }

    // ---- x1 = x_q + sigmoid(alpha1)*delta ----
    x1_k<<<EW_B, 256>>>(x_q, pDelta, alpha1, pX1);

    // ---- MLP with LoRA ----
    rmsnorm_k<<<MQ, 256>>>(pX1, ln2_w, pH, DD);

    // gate path
    gemm(false, MQ, FFD, DD, pH, DD, 0, 0, gate_w, FFD, 0, 0, pG, FFD, 0, 0, 1, 1, 1.f, 0.f, nullptr);
    gemm(false, MQ, RR, DD, pH, DD, 0, 0, la_gA, RR, 0, 0, pLt, RR, 0, 0, 1, 1, 1.f, 0.f, nullptr);
    gemm(false, MQ, FFD, RR, pLt, RR, 0, 0, la_gB, FFD, 0, 0, pG, FFD, 0, 0, 1, 1, LORA_SCALE, 1.f, nullptr);

    // up path
    gemm(false, MQ, FFD, DD, pH, DD, 0, 0, up_w, FFD, 0, 0, pU, FFD, 0, 0, 1, 1, 1.f, 0.f, nullptr);
    gemm(false, MQ, RR, DD, pH, DD, 0, 0, la_uA, RR, 0, 0, pLt, RR, 0, 0, 1, 1, 1.f, 0.f, nullptr);
    gemm(false, MQ, FFD, RR, pLt, RR, 0, 0, la_uB, FFD, 0, 0, pU, FFD, 0, 0, 1, 1, LORA_SCALE, 1.f, nullptr);

    // x_down = silu(gate) + up
    {
        long long n = (long long)MQ * FFD;
        int blocks = (int)((n + 255) / 256);
        silu_add_k<<<blocks, 256>>>(pG, pU, n);
    }

    // down path
    gemm(false, MQ, DD, FFD, pG, FFD, 0, 0, down_w, DD, 0, 0, pT, DD, 0, 0, 1, 1, 1.f, 0.f, nullptr);
    gemm(false, MQ, RR, FFD, pG, FFD, 0, 0, la_dA, RR, 0, 0, pLt, RR, 0, 0, 1, 1, 1.f, 0.f, nullptr);
    gemm(false, MQ, DD, RR, pLt, RR, 0, 0, la_dB, DD, 0, 0, pT, DD, 0, 0, 1, 1, LORA_SCALE, 1.f, nullptr);

    // out = x1 + sigmoid(alpha2)*mlp_out
    out_k<<<EW_B, 256>>>(pX1, pT, alpha2, out);
}